// round 11
// baseline (speedup 1.0000x reference)
#include <cuda_runtime.h>
#include <stdint.h>

#define NB 32
#define NT 15

// ---------------- device scratch (no cudaMalloc allowed) ----------------
static __device__ __align__(16) int8_t  g_ft1p[NB*90*15*16];   // pooled L1, row-stride 16
static __device__              uint8_t g_cflag1[NB*90];
static __device__              int     g_any1[NB];
static __device__              float   g_wsat2[250*36];        // SAT of channel-summed w2
static __device__              float   g_wsat3[200*36];        // SAT of channel-summed w3
static __device__              int8_t  g_excft[(size_t)NB*900*90]; // exact ft for exceptional pixels

// ===========================================================================
// conv1 slow path (rare): per-t rescan straight from input. Exact fp32.
__device__ __noinline__ int conv1_slow(const float* __restrict__ inp,
                                       int b, int f, int y, int x,
                                       const float* __restrict__ w1) {
    const float* wf = w1 + (size_t)f*882;
    for (int t = 1; t < 15; t++) {
        const float* pl = inp + ((size_t)(b*NT + t))*18*1024;
        float cum = 0.0f;
        for (int c = 0; c < 18; c++)
            for (int i = 0; i < 7; i++) {
                int h = y + i - 2;
                if ((unsigned)h >= 32u) continue;
                for (int j = 0; j < 7; j++) {
                    int w = x + j - 2;
                    if ((unsigned)w >= 32u) continue;
                    if (pl[(c << 10) + (h << 5) + w] > 0.5f) cum += wf[c*49 + i*7 + j];
                }
            }
        if (cum > 15.0f) return t;
    }
    return 15;
}

// ===========================================================================
// k_head: blocks [0,450) = weight SATs (proven); blocks [450,482) = conv1
// per batch (self-contained: inline wmin, self-zeroed outputs, direct any1).
__global__ __launch_bounds__(1024) void k_head(const float* __restrict__ inp,
                                               const float* __restrict__ w1,
                                               const float* __restrict__ w2,
                                               const float* __restrict__ w3) {
    __shared__ float    s_w[6250];
    __shared__ float    s_part[250];
    __shared__ float    s25[25];
    __shared__ float    s_red[1024];
    __shared__ uint64_t s_m[18*34];
    __shared__ uint16_t s_nt[960];
    __shared__ uint16_t s_elist[960];
    __shared__ int      s_ne;
    int bid = blockIdx.x, tid = threadIdx.x;

    if (bid < 450) {
        // ---- weight SAT (identical reduction order to proven version) ----
        const float* src; int C; float* dst; int f;
        if (bid < 250) { f = bid;     src = w2; C = 90;  dst = g_wsat2 + f*36; }
        else           { f = bid-250; src = w3; C = 250; dst = g_wsat3 + f*36; }
        const float* fsrc = src + (size_t)f*C*25;
        for (int i = tid; i < C*25; i += 1024) s_w[i] = fsrc[i];
        __syncthreads();
        if (tid < 250) {
            int p = tid / 10, g = tid % 10;
            float s = 0.0f;
            for (int c = g; c < C; c += 10) s += s_w[c*25 + p];
            s_part[p*10 + g] = s;
        }
        __syncthreads();
        if (tid < 25) {
            float s = 0.0f;
            for (int g = 0; g < 10; g++) s += s_part[tid*10 + g];
            s25[tid] = s;
        }
        __syncthreads();
        if (tid < 36) {
            int i = tid / 6, j = tid % 6;
            float s = 0.0f;
            for (int ii = 0; ii < i; ii++)
                for (int jj = 0; jj < j; jj++) s += s25[ii*5 + jj];
            dst[tid] = s;
        }
        return;
    }

    // ---- conv1 for batch b ----
    int b = bid - 450;
    // exact min(w1), order-invariant
    float m = 3.4e38f;
    for (int i = tid; i < 90*882; i += 1024) m = fminf(m, w1[i]);
    s_red[tid] = m;
    // zero own outputs while reduction settles
    {
        uint4* dst = (uint4*)(g_ft1p + (size_t)b*21600);
        for (int i = tid; i < 1350; i += 1024) dst[i] = make_uint4(0,0,0,0);
        if (tid < 90) g_cflag1[b*90 + tid] = 0;
    }
    if (tid == 0) s_ne = 0;
    // row bitmasks from the t=0 plane
    if (tid < 612) {
        int c = tid / 34, hh = tid % 34, h = hh - 2;
        uint64_t mask = 0;
        if ((unsigned)h < 32u) {
            const float4* row = (const float4*)(inp + ((size_t)b*NT*18 + c)*1024 + (h << 5));
            uint32_t bits = 0;
#pragma unroll
            for (int k = 0; k < 8; k++) {
                float4 v = row[k];
                bits |= (v.x > 0.5f ? 1u : 0u) << (k*4);
                bits |= (v.y > 0.5f ? 2u : 0u) << (k*4);
                bits |= (v.z > 0.5f ? 4u : 0u) << (k*4);
                bits |= (v.w > 0.5f ? 8u : 0u) << (k*4);
            }
            mask = ((uint64_t)bits) << 2;
        }
        s_m[tid] = mask;
    }
    if (tid < 960) s_nt[tid] = 0;
    __syncthreads();
    for (int s = 512; s > 0; s >>= 1) {
        if (tid < s) s_red[tid] = fminf(s_red[tid], s_red[tid+s]);
        __syncthreads();
    }
    float wmin = s_red[0];

    int y = tid >> 5, x = tid & 31;
    if (y < 30 && x < 30) {
        int nt = 0;
        for (int c = 0; c < 18; c++) {
            const uint64_t* base = s_m + c*34 + y;
#pragma unroll
            for (int i = 0; i < 7; i++)
                nt += __popc((uint32_t)(base[i] >> x) & 0x7Fu);
        }
        s_nt[tid] = (uint16_t)nt;
        if (!((float)nt * wmin > 15.0f)) {
            int sl = atomicAdd(&s_ne, 1);
            s_elist[sl] = (uint16_t)tid;
        }
    }
    __syncthreads();

    int ne = s_ne;
    for (int base = 0; base < ne; base += 11) {
        int slot = tid / 90, f = tid - slot*90;
        if (slot < 11 && base + slot < ne) {
            int pix = s_elist[base + slot];
            int yy = pix >> 5, xx = pix & 31;
            float pot0 = 0.0f;
            const float* wf = w1 + (size_t)f*882;
            for (int c = 0; c < 18; c++) {
                const uint64_t* mb = s_m + c*34 + yy;
#pragma unroll
                for (int i = 0; i < 7; i++) {
                    uint32_t wnd = (uint32_t)(mb[i] >> xx) & 0x7Fu;
                    const float* wr = wf + c*49 + i*7;
                    while (wnd) {
                        int p = __ffs(wnd) - 1;
                        wnd &= wnd - 1;
                        pot0 += __ldg(wr + p);
                    }
                }
            }
            int ft = (pot0 > 15.0f) ? 0 : conv1_slow(inp, b, f, yy, xx, w1);
            g_excft[((size_t)b*900 + yy*30 + xx)*90 + f] = (int8_t)ft;
        }
        __syncthreads();
    }

    bool nz = false;
    if (ne > 0 && tid < 225) {
        int py = tid / 15, px = tid % 15;
        int m00 = (py*2)*32 + px*2;
        int m01 = m00 + 1, m10 = m00 + 32, m11 = m10 + 1;
        bool e00 = !((float)s_nt[m00]*wmin > 15.0f);
        bool e01 = !((float)s_nt[m01]*wmin > 15.0f);
        bool e10 = !((float)s_nt[m10]*wmin > 15.0f);
        bool e11 = !((float)s_nt[m11]*wmin > 15.0f);
        if (e00 && e01 && e10 && e11) {
            int yy = py*2, xx = px*2;
            const int8_t* q00 = g_excft + ((size_t)b*900 + yy*30     + xx    )*90;
            const int8_t* q01 = g_excft + ((size_t)b*900 + yy*30     + xx + 1)*90;
            const int8_t* q10 = g_excft + ((size_t)b*900 + (yy+1)*30 + xx    )*90;
            const int8_t* q11 = g_excft + ((size_t)b*900 + (yy+1)*30 + xx + 1)*90;
            for (int f = 0; f < 90; f++) {
                int v0 = q00[f], v1 = q01[f], v2 = q10[f], v3 = q11[f];
                int m0 = v0 < v1 ? v0 : v1;
                int m1 = v2 < v3 ? v2 : v3;
                int pv = m0 < m1 ? m0 : m1;
                if (pv) {
                    g_ft1p[((b*90 + f)*15 + py)*16 + px] = (int8_t)pv;
                    g_cflag1[b*90 + f] = 1;
                    nz = true;
                }
            }
        }
    }
    int cnt = __syncthreads_count(nz);
    if (tid == 0) g_any1[b] = cnt ? 1 : 0;
}

// ===========================================================================
// k_tail: per-batch conv2 + pool2 + conv3 + winner in ONE block (1024 thr).
// Layout in dynamic smem:
#define T_SAT2  0            // 9000 f32
#define T_SAT3  36000        // 7200 f32
#define T_FT2   64800        // 42250 i8 (pad to 107056)
#define T_FTP2  107056       // 4000 i8
#define T_FLAG1 111056       // 90 u8
#define T_FLAG2 111146       // 250 u8 (pad to 111400)
#define T_KEY   111400       // 1024 u64
#define TAIL_SMEM 119616
extern __shared__ unsigned char smem_raw[];
__global__ __launch_bounds__(1024) void k_tail(const float* __restrict__ w2,
                                               const float* __restrict__ w3,
                                               float* __restrict__ pot,
                                               float* __restrict__ cls) {
    float*    s_sat2 = (float*)(smem_raw + T_SAT2);
    float*    s_sat3 = (float*)(smem_raw + T_SAT3);
    int8_t*   s_ft2  = (int8_t*)(smem_raw + T_FT2);
    int8_t*   s_ftp2 = (int8_t*)(smem_raw + T_FTP2);
    uint8_t*  s_flag1 = (uint8_t*)(smem_raw + T_FLAG1);
    uint8_t*  s_flag2 = (uint8_t*)(smem_raw + T_FLAG2);
    unsigned long long* s_key = (unsigned long long*)(smem_raw + T_KEY);

    int b = blockIdx.x, tid = threadIdx.x;
    int any1 = g_any1[b];

    for (int i = tid; i < 9000; i += 1024) s_sat2[i] = g_wsat2[i];
    for (int i = tid; i < 7200; i += 1024) s_sat3[i] = g_wsat3[i];
    if (tid < 90)  s_flag1[tid] = any1 ? g_cflag1[b*90 + tid] : 0;
    if (tid < 250) s_flag2[tid] = 0;
    __syncthreads();

    // ---- conv2: 250 filters x 169 pixels ----
    for (int o = tid; o < 42250; o += 1024) {
        int f = o / 169, pix = o - f*169;
        int y = pix / 13, x = pix - y*13;
        int r0 = max(0, y-1), r1 = min(14, y+3);
        int c0 = max(0, x-1), c1 = min(14, x+3);
        int i0 = r0 - (y-1), i1 = r1 - (y-1);
        int j0 = c0 - (x-1), j1 = c1 - (x-1);
        const float* S = s_sat2 + f*36;
        float a0 = S[(i1+1)*6 + (j1+1)] - S[i0*6 + (j1+1)]
                 - S[(i1+1)*6 + j0]     + S[i0*6 + j0];
        int ft;
        if (!any1) {
            ft = (a0 > 10.0f) ? 0 : 15;
        } else {
            float def[15];
#pragma unroll
            for (int t = 0; t < 15; t++) def[t] = 0.f;
            for (int c = 0; c < 90; c++) {
                if (!s_flag1[c]) continue;
                const int8_t* tp = g_ft1p + (size_t)(b*90 + c)*240;
                const float*  wp = w2 + ((size_t)f*90 + c)*25;
                for (int r = r0; r <= r1; r++)
                    for (int cc = c0; cc <= c1; cc++) {
                        int tf = tp[r*16 + cc];
                        if (tf) {
                            float wv = __ldg(wp + (r-(y-1))*5 + (cc-(x-1)));
#pragma unroll
                            for (int t = 0; t < 15; t++) def[t] += (tf > t) ? wv : 0.f;
                        }
                    }
            }
            ft = 15;
#pragma unroll
            for (int t = 14; t >= 0; t--) if (a0 - def[t] > 10.0f) ft = t;
        }
        s_ft2[o] = (int8_t)ft;
    }
    __syncthreads();

    // ---- pool2: 3x3 s3 min + flags ----
    bool nz = false;
    for (int i = tid; i < 4000; i += 1024) {
        int f = i >> 4, p = i & 15;
        int y = (p >> 2)*3, x = (p & 3)*3;
        const int8_t* bp = s_ft2 + f*169 + y*13 + x;
        int v = 15;
#pragma unroll
        for (int dy = 0; dy < 3; dy++)
#pragma unroll
            for (int dx = 0; dx < 3; dx++) {
                int u = bp[dy*13 + dx];
                v = u < v ? u : v;
            }
        s_ftp2[i] = (int8_t)v;
        if (v) { s_flag2[f] = 1; nz = true; }
    }
    int any2 = __syncthreads_count(nz);

    // ---- conv3 + winner candidates ----
    unsigned long long bestkey = 0ull;
    for (int o = tid; o < 3200; o += 1024) {
        int f = o >> 4, p = o & 15;
        int y = p >> 2, x = p & 3;
        int r0 = max(0, y-2), r1 = min(3, y+2);
        int c0 = max(0, x-2), c1 = min(3, x+2);
        int i0 = r0 - (y-2), i1 = r1 - (y-2);
        int j0 = c0 - (x-2), j1 = c1 - (x-2);
        const float* S = s_sat3 + f*36;
        float a0 = S[(i1+1)*6 + (j1+1)] - S[i0*6 + (j1+1)]
                 - S[(i1+1)*6 + j0]     + S[i0*6 + j0];
        float* op = pot + (size_t)b*NT*3200 + o;
        float last;
        if (!any2) {
#pragma unroll
            for (int t = 0; t < NT; t++) op[(size_t)t*3200] = a0;
            last = a0;
        } else {
            float def[15];
#pragma unroll
            for (int t = 0; t < 15; t++) def[t] = 0.f;
            for (int c = 0; c < 250; c++) {
                if (!s_flag2[c]) continue;
                const int8_t* tp = s_ftp2 + c*16;
                const float*  wp = w3 + ((size_t)f*250 + c)*25;
                for (int r = r0; r <= r1; r++)
                    for (int cc = c0; cc <= c1; cc++) {
                        int tf = tp[r*4 + cc];
                        if (tf) {
                            float wv = __ldg(wp + (r-(y-2))*5 + (cc-(x-2)));
#pragma unroll
                            for (int t = 0; t < 15; t++) def[t] += (tf > t) ? wv : 0.f;
                        }
                    }
            }
#pragma unroll
            for (int t = 0; t < NT; t++) op[(size_t)t*3200] = a0 - def[t];
            last = a0 - def[14];
        }
        if (last > 0.0f) {
            unsigned long long key =
                ((unsigned long long)__float_as_uint(last) << 32)
                | (unsigned)(~o);
            if (key > bestkey) bestkey = key;
        }
    }

    if (cls) {
        s_key[tid] = bestkey;
        __syncthreads();
        for (int s = 512; s > 0; s >>= 1) {
            if (tid < s) {
                unsigned long long o2 = s_key[tid+s];
                if (o2 > s_key[tid]) s_key[tid] = o2;
            }
            __syncthreads();
        }
        if (tid == 0) {
            unsigned long long k = s_key[0];
            if (k == 0ull) cls[b] = -1.0f;
            else {
                unsigned idx = ~(unsigned)(k & 0xFFFFFFFFu);
                cls[b] = (float)((idx >> 4) / 20);
            }
        }
    }
}

// ===========================================================================
extern "C" void kernel_launch(void* const* d_in, const int* in_sizes, int n_in,
                              void* d_out, int out_size) {
    const float* inp = (const float*)d_in[0];
    const float* w1  = (const float*)d_in[1];
    const float* w2  = (const float*)d_in[2];
    const float* w3  = (const float*)d_in[3];

    float* out = (float*)d_out;
    float* pot = out;
    float* cls = nullptr;
    if (out_size == NB + NB*NT*3200) {   // (cls, pot3) concatenated
        cls = out;
        pot = out + NB;
    }

    static bool attr_set = false;
    if (!attr_set) {
        cudaFuncSetAttribute(k_tail, cudaFuncAttributeMaxDynamicSharedMemorySize,
                             TAIL_SMEM);
        attr_set = true;
    }

    k_head<<<482, 1024>>>(inp, w1, w2, w3);
    k_tail<<<NB, 1024, TAIL_SMEM>>>(w2, w3, pot, cls);
}

// round 12
// speedup vs baseline: 1.1835x; 1.1835x over previous
#include <cuda_runtime.h>
#include <stdint.h>

#define NB 32
#define NT 15

// ---------------- device scratch (no cudaMalloc allowed) ----------------
static __device__ __align__(16) int8_t  g_ft1p[NB*90*15*16];   // pooled L1, row-stride 16
static __device__              uint8_t g_cflag1[NB*90];
static __device__              int     g_any1[NB];
static __device__              float   g_wsat2[250*36];        // SAT of channel-summed w2 ([35]=total)
static __device__              float   g_wsat3[200*36];        // SAT of channel-summed w3
static __device__              int8_t  g_excft[(size_t)NB*900*90]; // exact ft for exceptional pixels
static __device__              unsigned long long g_best[NB];  // winner keys
static __device__              int     g_done[NB];             // tail done counters

// ===========================================================================
// conv1 slow path (rare): per-t rescan straight from input. Exact fp32.
__device__ __noinline__ int conv1_slow(const float* __restrict__ inp,
                                       int b, int f, int y, int x,
                                       const float* __restrict__ w1) {
    const float* wf = w1 + (size_t)f*882;
    for (int t = 1; t < 15; t++) {
        const float* pl = inp + ((size_t)(b*NT + t))*18*1024;
        float cum = 0.0f;
        for (int c = 0; c < 18; c++)
            for (int i = 0; i < 7; i++) {
                int h = y + i - 2;
                if ((unsigned)h >= 32u) continue;
                for (int j = 0; j < 7; j++) {
                    int w = x + j - 2;
                    if ((unsigned)w >= 32u) continue;
                    if (pl[(c << 10) + (h << 5) + w] > 0.5f) cum += wf[c*49 + i*7 + j];
                }
            }
        if (cum > 15.0f) return t;
    }
    return 15;
}

// ===========================================================================
// k_head: [0,450) weight SATs | [450,482) conv1 per batch | 482 zero best/done.
__global__ __launch_bounds__(1024) void k_head(const float* __restrict__ inp,
                                               const float* __restrict__ w1,
                                               const float* __restrict__ w2,
                                               const float* __restrict__ w3) {
    __shared__ float    s_w[6250];
    __shared__ float    s_part[250];
    __shared__ float    s25[25];
    __shared__ float    s_red[1024];
    __shared__ uint64_t s_m[18*34];
    __shared__ uint16_t s_nt[960];
    __shared__ uint16_t s_elist[960];
    __shared__ int      s_ne;
    int bid = blockIdx.x, tid = threadIdx.x;

    if (bid < 450) {
        const float* src; int C; float* dst; int f;
        if (bid < 250) { f = bid;     src = w2; C = 90;  dst = g_wsat2 + f*36; }
        else           { f = bid-250; src = w3; C = 250; dst = g_wsat3 + f*36; }
        const float* fsrc = src + (size_t)f*C*25;
        for (int i = tid; i < C*25; i += 1024) s_w[i] = fsrc[i];
        __syncthreads();
        if (tid < 250) {
            int p = tid / 10, g = tid % 10;
            float s = 0.0f;
            for (int c = g; c < C; c += 10) s += s_w[c*25 + p];
            s_part[p*10 + g] = s;
        }
        __syncthreads();
        if (tid < 25) {
            float s = 0.0f;
            for (int g = 0; g < 10; g++) s += s_part[tid*10 + g];
            s25[tid] = s;
        }
        __syncthreads();
        if (tid < 36) {
            int i = tid / 6, j = tid % 6;
            float s = 0.0f;
            for (int ii = 0; ii < i; ii++)
                for (int jj = 0; jj < j; jj++) s += s25[ii*5 + jj];
            dst[tid] = s;
        }
        return;
    }
    if (bid == 482) {
        if (tid < NB) { g_best[tid] = 0ull; g_done[tid] = 0; }
        return;
    }

    // ---- conv1 for batch b (R9/R11 proven) ----
    int b = bid - 450;
    float m = 3.4e38f;
    for (int i = tid; i < 90*882; i += 1024) m = fminf(m, w1[i]);
    s_red[tid] = m;
    {
        uint4* dst = (uint4*)(g_ft1p + (size_t)b*21600);
        for (int i = tid; i < 1350; i += 1024) dst[i] = make_uint4(0,0,0,0);
        if (tid < 90) g_cflag1[b*90 + tid] = 0;
    }
    if (tid == 0) s_ne = 0;
    if (tid < 612) {
        int c = tid / 34, hh = tid % 34, h = hh - 2;
        uint64_t mask = 0;
        if ((unsigned)h < 32u) {
            const float4* row = (const float4*)(inp + ((size_t)b*NT*18 + c)*1024 + (h << 5));
            uint32_t bits = 0;
#pragma unroll
            for (int k = 0; k < 8; k++) {
                float4 v = row[k];
                bits |= (v.x > 0.5f ? 1u : 0u) << (k*4);
                bits |= (v.y > 0.5f ? 2u : 0u) << (k*4);
                bits |= (v.z > 0.5f ? 4u : 0u) << (k*4);
                bits |= (v.w > 0.5f ? 8u : 0u) << (k*4);
            }
            mask = ((uint64_t)bits) << 2;
        }
        s_m[tid] = mask;
    }
    if (tid < 960) s_nt[tid] = 0;
    __syncthreads();
    for (int s = 512; s > 0; s >>= 1) {
        if (tid < s) s_red[tid] = fminf(s_red[tid], s_red[tid+s]);
        __syncthreads();
    }
    float wmin = s_red[0];

    int y = tid >> 5, x = tid & 31;
    if (y < 30 && x < 30) {
        int nt = 0;
        for (int c = 0; c < 18; c++) {
            const uint64_t* base = s_m + c*34 + y;
#pragma unroll
            for (int i = 0; i < 7; i++)
                nt += __popc((uint32_t)(base[i] >> x) & 0x7Fu);
        }
        s_nt[tid] = (uint16_t)nt;
        if (!((float)nt * wmin > 15.0f)) {
            int sl = atomicAdd(&s_ne, 1);
            s_elist[sl] = (uint16_t)tid;
        }
    }
    __syncthreads();

    int ne = s_ne;
    for (int base = 0; base < ne; base += 11) {
        int slot = tid / 90, f = tid - slot*90;
        if (slot < 11 && base + slot < ne) {
            int pix = s_elist[base + slot];
            int yy = pix >> 5, xx = pix & 31;
            float pot0 = 0.0f;
            const float* wf = w1 + (size_t)f*882;
            for (int c = 0; c < 18; c++) {
                const uint64_t* mb = s_m + c*34 + yy;
#pragma unroll
                for (int i = 0; i < 7; i++) {
                    uint32_t wnd = (uint32_t)(mb[i] >> xx) & 0x7Fu;
                    const float* wr = wf + c*49 + i*7;
                    while (wnd) {
                        int p = __ffs(wnd) - 1;
                        wnd &= wnd - 1;
                        pot0 += __ldg(wr + p);
                    }
                }
            }
            int ft = (pot0 > 15.0f) ? 0 : conv1_slow(inp, b, f, yy, xx, w1);
            g_excft[((size_t)b*900 + yy*30 + xx)*90 + f] = (int8_t)ft;
        }
        __syncthreads();
    }

    bool nz = false;
    if (ne > 0 && tid < 225) {
        int py = tid / 15, px = tid % 15;
        int m00 = (py*2)*32 + px*2;
        int m01 = m00 + 1, m10 = m00 + 32, m11 = m10 + 1;
        bool e00 = !((float)s_nt[m00]*wmin > 15.0f);
        bool e01 = !((float)s_nt[m01]*wmin > 15.0f);
        bool e10 = !((float)s_nt[m10]*wmin > 15.0f);
        bool e11 = !((float)s_nt[m11]*wmin > 15.0f);
        if (e00 && e01 && e10 && e11) {
            int yy = py*2, xx = px*2;
            const int8_t* q00 = g_excft + ((size_t)b*900 + yy*30     + xx    )*90;
            const int8_t* q01 = g_excft + ((size_t)b*900 + yy*30     + xx + 1)*90;
            const int8_t* q10 = g_excft + ((size_t)b*900 + (yy+1)*30 + xx    )*90;
            const int8_t* q11 = g_excft + ((size_t)b*900 + (yy+1)*30 + xx + 1)*90;
            for (int f = 0; f < 90; f++) {
                int v0 = q00[f], v1 = q01[f], v2 = q10[f], v3 = q11[f];
                int m0 = v0 < v1 ? v0 : v1;
                int m1 = v2 < v3 ? v2 : v3;
                int pv = m0 < m1 ? m0 : m1;
                if (pv) {
                    g_ft1p[((b*90 + f)*15 + py)*16 + px] = (int8_t)pv;
                    g_cflag1[b*90 + f] = 1;
                    nz = true;
                }
            }
        }
    }
    int cnt = __syncthreads_count(nz);
    if (tid == 0) g_any1[b] = cnt ? 1 : 0;
}

// ===========================================================================
// generic conv2 fire time at (filter f2, pixel y,x) — only on the never-taken
// fallback path. Exact: SAT rect + per-channel corrections + threshold scan.
__device__ __noinline__ int conv2_ft_generic(const float* __restrict__ w2,
                                             const uint8_t* __restrict__ flag1,
                                             int b, int f2, int y, int x, int any1) {
    int r0 = max(0, y-1), r1 = min(14, y+3);
    int c0 = max(0, x-1), c1 = min(14, x+3);
    int i0 = r0 - (y-1), i1 = r1 - (y-1);
    int j0 = c0 - (x-1), j1 = c1 - (x-1);
    const float* S = g_wsat2 + f2*36;
    float a0 = S[(i1+1)*6 + (j1+1)] - S[i0*6 + (j1+1)]
             - S[(i1+1)*6 + j0]     + S[i0*6 + j0];
    if (!any1) return (a0 > 10.0f) ? 0 : 15;
    float def[15];
#pragma unroll
    for (int t = 0; t < 15; t++) def[t] = 0.f;
    for (int c = 0; c < 90; c++) {
        if (!flag1[c]) continue;
        const int8_t* tp = g_ft1p + (size_t)(b*90 + c)*240;
        const float*  wp = w2 + ((size_t)f2*90 + c)*25;
        for (int r = r0; r <= r1; r++)
            for (int cc = c0; cc <= c1; cc++) {
                int tf = tp[r*16 + cc];
                if (tf) {
                    float wv = __ldg(wp + (r-(y-1))*5 + (cc-(x-1)));
#pragma unroll
                    for (int t = 0; t < 15; t++) def[t] += (tf > t) ? wv : 0.f;
                }
            }
    }
    int ft = 15;
#pragma unroll
    for (int t = 14; t >= 0; t--) if (a0 - def[t] > 10.0f) ft = t;
    return ft;
}

// ===========================================================================
// k_tail2: grid (13, NB), 256 threads. Fast path: every pool window contains
// an interior conv2 pixel whose potential equals total2(f) = g_wsat2[f*36+35];
// if any1==0 and all totals > thr, all pooled ft2p are 0 => conv3 = pure SAT.
// Generic fallback recomputes ft2p per block (redundant, correct, never hit).
__global__ __launch_bounds__(256) void k_tail2(const float* __restrict__ w2,
                                               const float* __restrict__ w3,
                                               float* __restrict__ pot,
                                               float* __restrict__ cls) {
    __shared__ float   s_sat3[16*36];
    __shared__ int8_t  s_ftp2[250*16];
    __shared__ uint8_t s_flag1[90];
    __shared__ uint8_t s_flag2[250];
    __shared__ unsigned long long s_k[256];
    int tid = threadIdx.x;
    int fg = blockIdx.x, b = blockIdx.y;
    int any1 = g_any1[b];

    bool ok = (tid < 250) ? (g_wsat2[tid*36 + 35] > 10.0f) : true;
    int nall = __syncthreads_count(ok);
    int generic = (any1 != 0) || (nall != 256);

    for (int i = tid; i < 16*36; i += 256) {
        int f = fg*16 + i/36;
        s_sat3[i] = (f < 200) ? g_wsat3[f*36 + i%36] : 0.0f;
    }
    if (tid < 90)  s_flag1[tid] = any1 ? g_cflag1[b*90 + tid] : 0;
    if (tid < 250) s_flag2[tid] = 0;
    __syncthreads();

    if (generic) {
        for (int e = tid; e < 4000; e += 256) {
            int c = e >> 4, pp = e & 15;
            int pyy = (pp >> 2)*3, pxx = (pp & 3)*3;
            int v = 15;
            for (int dy = 0; dy < 3; dy++)
                for (int dx = 0; dx < 3; dx++) {
                    int u = conv2_ft_generic(w2, s_flag1, b, c, pyy+dy, pxx+dx, any1);
                    v = u < v ? u : v;
                }
            s_ftp2[e] = (int8_t)v;
            if (v) s_flag2[c] = 1;
        }
        __syncthreads();
    }

    // ---- conv3 + winner candidate ----
    int fi = tid >> 4, p = tid & 15;
    int f = fg*16 + fi;
    unsigned long long key = 0ull;
    if (f < 200) {
        int y = p >> 2, x = p & 3;
        int r0 = max(0, y-2), r1 = min(3, y+2);
        int c0 = max(0, x-2), c1 = min(3, x+2);
        int i0 = r0 - (y-2), i1 = r1 - (y-2);
        int j0 = c0 - (x-2), j1 = c1 - (x-2);
        const float* S = s_sat3 + fi*36;
        float a0 = S[(i1+1)*6 + (j1+1)] - S[i0*6 + (j1+1)]
                 - S[(i1+1)*6 + j0]     + S[i0*6 + j0];
        float* o = pot + ((size_t)b*NT*200 + f)*16 + p;
        float last;
        if (!generic) {
#pragma unroll
            for (int t = 0; t < NT; t++) o[(size_t)t * 3200] = a0;
            last = a0;
        } else {
            float def[15];
#pragma unroll
            for (int t = 0; t < 15; t++) def[t] = 0.f;
            for (int c = 0; c < 250; c++) {
                if (!s_flag2[c]) continue;
                const int8_t* tp = s_ftp2 + c*16;
                const float*  wp = w3 + ((size_t)f*250 + c)*25;
                for (int r = r0; r <= r1; r++)
                    for (int cc = c0; cc <= c1; cc++) {
                        int tf = tp[r*4 + cc];
                        if (tf) {
                            float wv = __ldg(wp + (r-(y-2))*5 + (cc-(x-2)));
#pragma unroll
                            for (int t = 0; t < 15; t++) def[t] += (tf > t) ? wv : 0.f;
                        }
                    }
            }
#pragma unroll
            for (int t = 0; t < NT; t++) o[(size_t)t * 3200] = a0 - def[t];
            last = a0 - def[14];
        }
        if (last > 0.0f)
            key = ((unsigned long long)__float_as_uint(last) << 32)
                | (unsigned)(~(f*16 + p));
    }
    s_k[tid] = key;
    __syncthreads();
    for (int s = 128; s > 0; s >>= 1) {
        if (tid < s) {
            unsigned long long o2 = s_k[tid+s];
            if (o2 > s_k[tid]) s_k[tid] = o2;
        }
        __syncthreads();
    }
    if (tid == 0 && cls) {
        if (s_k[0]) atomicMax(&g_best[b], s_k[0]);
        __threadfence();
        int d = atomicAdd(&g_done[b], 1);
        if (d == 12) {                       // last of 13 blocks for batch b
            __threadfence();
            unsigned long long bestk = g_best[b];
            if (bestk == 0ull) cls[b] = -1.0f;
            else {
                unsigned idx = ~(unsigned)(bestk & 0xFFFFFFFFu);
                cls[b] = (float)((idx >> 4) / 20);
            }
        }
    }
}

// ===========================================================================
extern "C" void kernel_launch(void* const* d_in, const int* in_sizes, int n_in,
                              void* d_out, int out_size) {
    const float* inp = (const float*)d_in[0];
    const float* w1  = (const float*)d_in[1];
    const float* w2  = (const float*)d_in[2];
    const float* w3  = (const float*)d_in[3];

    float* out = (float*)d_out;
    float* pot = out;
    float* cls = nullptr;
    if (out_size == NB + NB*NT*3200) {   // (cls, pot3) concatenated
        cls = out;
        pot = out + NB;
    }

    k_head <<<483, 1024>>>(inp, w1, w2, w3);
    k_tail2<<<dim3(13, NB), 256>>>(w2, w3, pot, cls);
}